// round 1
// baseline (speedup 1.0000x reference)
#include <cuda_runtime.h>
#include <math.h>

#define BD 4
#define LL 4096
#define PX (BD*LL)        // 16384 pixels
#define CM 192
#define DI 384
#define RK 12
#define NS 16
#define NC 8              // scan chunks
#define LC (LL/NC)        // 512
#define TT 64             // scan sub-tile

// ---------------- scratch (device globals; no mallocs allowed) ----------------
__device__ float d_xn   [PX*CM];
__device__ float d_xz   [(size_t)PX*2*DI];
__device__ float d_lowp [(size_t)PX*DI];
__device__ float d_xs   [(size_t)PX*DI];     // u, pixel-major [p][d]
__device__ float d_ut   [(size_t)BD*DI*LL];  // u, channel-major [b][d][l]
__device__ float d_deltaT[(size_t)BD*DI*LL]; // delta, channel-major
__device__ float d_xdbl [PX*64];
__device__ float d_ldbl [PX*64];
__device__ float d_dts0 [PX*16];
__device__ float d_Bs0  [PX*16];
__device__ float d_Cs0  [PX*16];
__device__ float d_dts1 [PX*16];
__device__ float d_Bs1  [PX*16];
__device__ float d_Cs1  [PX*16];
__device__ float d_y    [(size_t)PX*DI];
__device__ float d_gated[(size_t)PX*DI];
__device__ float d_Wt1  [CM*2*DI];   // in_proj^T  [k][co]
__device__ float d_Wt2  [CM*DI];     // in_proj_low^T
__device__ float d_Wt3  [DI*CM];     // out_proj^T
__device__ float d_Wtx  [DI*64];     // x_proj^T padded to 64 cols
__device__ float d_Wtxl [DI*64];     // x_proj_low^T padded
__device__ float d_hfin [BD*NC*DI*NS];
__device__ float d_dsum [BD*NC*DI];
__device__ float d_hin  [BD*NC*DI*NS];

// ---------------- weight prep: transpose to k-major ----------------
__global__ void k_prep(const float* __restrict__ ipw, const float* __restrict__ iplw,
                       const float* __restrict__ opw, const float* __restrict__ xpw,
                       const float* __restrict__ xpwl) {
    int i = blockIdx.x*blockDim.x + threadIdx.x;
    const int n1 = CM*2*DI, n2 = CM*DI, n3 = DI*CM, n4 = DI*64;
    if (i < n1) { int k=i/(2*DI), co=i%(2*DI); d_Wt1[i]=ipw[co*CM+k]; return; }
    i -= n1;
    if (i < n2) { int k=i/DI, co=i%DI; d_Wt2[i]=iplw[co*CM+k]; return; }
    i -= n2;
    if (i < n3) { int k=i/CM, co=i%CM; d_Wt3[i]=opw[co*DI+k]; return; }
    i -= n3;
    if (i < n4) { int k=i/64, co=i%64; d_Wtx[i]=(co<44)? xpw[co*DI+k]:0.f; return; }
    i -= n4;
    if (i < n4) { int k=i/64, co=i%64; d_Wtxl[i]=(co<44)? xpwl[co*DI+k]:0.f; return; }
}

// ---------------- LayerNorm (warp per pixel) ----------------
__global__ void k_ln(const float* __restrict__ x, const float* __restrict__ g,
                     const float* __restrict__ b) {
    int wid = threadIdx.x>>5, lane = threadIdx.x&31;
    int p = blockIdx.x*8 + wid;
    const float* row = x + (size_t)p*CM;
    float s=0.f, s2=0.f;
    for (int c=lane;c<CM;c+=32){ float v=row[c]; s+=v; s2+=v*v; }
    for (int o=16;o;o>>=1){ s+=__shfl_xor_sync(~0u,s,o); s2+=__shfl_xor_sync(~0u,s2,o); }
    float mean = s/CM, var = s2/CM - mean*mean;
    float rstd = rsqrtf(var + 1e-5f);
    for (int c=lane;c<CM;c+=32)
        d_xn[(size_t)p*CM+c] = (row[c]-mean)*rstd*g[c]+b[c];
}

// ---------------- generic 64x64 GEMM: C[M,N] = A[M,K] * W[K,N] (+resid) ----------------
__global__ void k_gemm(const float* __restrict__ A, const float* __restrict__ W,
                       float* __restrict__ C, int K, int N,
                       const float* __restrict__ resid) {
    __shared__ float As[32][68];
    __shared__ float Bs[32][64];
    int m0 = blockIdx.y*64, n0 = blockIdx.x*64;
    int tid = threadIdx.x;
    int tx = tid&15, ty = tid>>4;
    float acc[4][4];
    #pragma unroll
    for (int i=0;i<4;i++)
        #pragma unroll
        for (int j=0;j<4;j++) acc[i][j]=0.f;
    for (int k0=0;k0<K;k0+=32) {
        __syncthreads();
        #pragma unroll
        for (int r=0;r<8;r++){ int j=tid+r*256; int m=j>>5, kk=j&31;
            As[kk][m] = A[(size_t)(m0+m)*K + k0+kk]; }
        #pragma unroll
        for (int r=0;r<8;r++){ int j=tid+r*256; int kk=j>>6, n=j&63;
            Bs[kk][n] = W[(size_t)(k0+kk)*N + n0+n]; }
        __syncthreads();
        #pragma unroll
        for (int kk=0;kk<32;kk++){
            float4 a4 = *(const float4*)&As[kk][ty*4];
            float4 b4 = *(const float4*)&Bs[kk][tx*4];
            float av[4]={a4.x,a4.y,a4.z,a4.w};
            float bv[4]={b4.x,b4.y,b4.z,b4.w};
            #pragma unroll
            for (int i=0;i<4;i++)
                #pragma unroll
                for (int j=0;j<4;j++) acc[i][j] = fmaf(av[i],bv[j],acc[i][j]);
        }
    }
    #pragma unroll
    for (int i=0;i<4;i++){
        int m = m0+ty*4+i;
        #pragma unroll
        for (int j=0;j<4;j++){
            int n = n0+tx*4+j;
            float v = acc[i][j];
            if (resid) v += resid[(size_t)m*N+n];
            C[(size_t)m*N+n] = v;
        }
    }
}

// ---------------- depthwise 3x3 conv + bias + SiLU ----------------
__global__ void k_conv2d(const float* __restrict__ w, const float* __restrict__ bias) {
    int idx = blockIdx.x*blockDim.x + threadIdx.x;          // PX*DI
    int d = idx % DI; int l = (idx/DI) & (LL-1); int b = idx/(DI*LL);
    int h = l>>6, wc = l&63;
    float acc = bias[d];
    #pragma unroll
    for (int dy=0;dy<3;dy++){
        int hh = h+dy-1; if ((unsigned)hh >= 64u) continue;
        #pragma unroll
        for (int dx=0;dx<3;dx++){
            int ww = wc+dx-1; if ((unsigned)ww >= 64u) continue;
            acc = fmaf(w[d*9+dy*3+dx],
                       d_xz[((size_t)(b*LL + (hh<<6)+ww))*(2*DI) + d], acc);
        }
    }
    d_xs[(size_t)(b*LL+l)*DI + d] = acc / (1.f + __expf(-acc));
}

// ---------------- transpose u: [b][l][d] -> [b][d][l] ----------------
__global__ void k_transpose() {
    __shared__ float t[32][33];
    int b = blockIdx.z, l0 = blockIdx.y*32, d0 = blockIdx.x*32;
    int tx = threadIdx.x, ty = threadIdx.y;
    #pragma unroll
    for (int r=0;r<32;r+=8)
        t[ty+r][tx] = d_xs[(size_t)(b*LL + l0+ty+r)*DI + d0+tx];
    __syncthreads();
    #pragma unroll
    for (int r=0;r<32;r+=8)
        d_ut[((size_t)b*DI + d0+ty+r)*LL + l0+tx] = t[tx][ty+r];
}

// ---------------- combine branches + SimpleGate on low B/C ----------------
__global__ void k_combine(const float* __restrict__ w1b, const float* __restrict__ w2b,
                          const float* __restrict__ w1c, const float* __restrict__ w2c) {
    __shared__ float s_w1b[192*16], s_w2b[16*96], s_w1c[192*16], s_w2c[16*96];
    int tid = threadIdx.x;
    for (int i=tid;i<192*16;i+=256){ s_w1b[i]=w1b[i]; s_w1c[i]=w1c[i]; }
    for (int i=tid;i<16*96;i+=256){ s_w2b[i]=w2b[i]; s_w2c[i]=w2c[i]; }
    __syncthreads();
    int gi = blockIdx.x*256 + tid;                          // 2*PX
    int p = gi>>1, br = gi&1;
    const float* xd = d_xdbl + (size_t)p*64;
    const float* ld = d_ldbl + (size_t)p*64;
    const float* w1 = br? s_w1c : s_w1b;
    const float* w2 = br? s_w2c : s_w2b;
    int off = br? 28 : 12;
    float xv[16], acc[16];
    #pragma unroll
    for (int c=0;c<16;c++){ xv[c]=ld[off+c]; acc[c]=0.f; }
    for (int hh=0;hh<96;hh++){
        float y1=0.f, y2=0.f;
        #pragma unroll
        for (int c=0;c<16;c++){
            y1 = fmaf(w1[hh*16+c], xv[c], y1);
            y2 = fmaf(w1[(hh+96)*16+c], xv[c], y2);
        }
        float g = 0.5f*y1*(1.f+erff(y1*0.70710678118f))*y2;
        #pragma unroll
        for (int c=0;c<16;c++) acc[c] = fmaf(g, w2[c*96+hh], acc[c]);
    }
    float* outp = br? d_Cs0 : d_Bs0;
    #pragma unroll
    for (int c=0;c<16;c++) outp[(size_t)p*16+c] = xd[off+c] + acc[c];
    if (br==0){
        #pragma unroll
        for (int r=0;r<16;r++)
            d_dts0[(size_t)p*16+r] = (r<12)? (xd[r]+ld[r]) : 0.f;
    }
}

// ---------------- residual dilated (dil=2, K=15) depthwise conv1d ----------------
__global__ void k_dwconv1d(const float* __restrict__ wdt, const float* __restrict__ wB,
                           const float* __restrict__ wC) {
    int idx = blockIdx.x*blockDim.x + threadIdx.x;          // 3 * BD*LL*16
    const int per = BD*LL*16;
    int t = idx / per; int rem = idx % per;
    int c = rem & 15; int l = (rem>>4) & (LL-1); int b = rem >> 16;
    const float* in; float* out; const float* w; int nc;
    if (t==0){ in=d_dts0; out=d_dts1; w=wdt; nc=12; }
    else if (t==1){ in=d_Bs0; out=d_Bs1; w=wB; nc=16; }
    else { in=d_Cs0; out=d_Cs1; w=wC; nc=16; }
    size_t base = (size_t)b*LL*16;
    if (c < nc){
        float accv = in[base + (size_t)l*16 + c];
        #pragma unroll
        for (int k=0;k<15;k++){
            int ll = l + 2*k - 14;
            if ((unsigned)ll < (unsigned)LL)
                accv = fmaf(w[c*15+k], in[base + (size_t)ll*16 + c], accv);
        }
        out[base + (size_t)l*16 + c] = accv;
    } else out[base + (size_t)l*16 + c] = 0.f;
}

// ---------------- delta = softplus(dts @ dt_w^T + b), write channel-major ----------------
__global__ void k_delta(const float* __restrict__ dtw, const float* __restrict__ dtb) {
    int idx = blockIdx.x*blockDim.x + threadIdx.x;          // BD*DI*LL
    int l = idx & (LL-1); int t = idx >> 12; int d = t % DI; int b = t / DI;
    const float* row = d_dts1 + ((size_t)b*LL + l)*16;
    float acc = dtb[d];
    #pragma unroll
    for (int r=0;r<12;r++) acc = fmaf(row[r], dtw[d*12+r], acc);
    float sp = (acc > 20.f)? acc : log1pf(expf(acc));
    d_deltaT[((size_t)b*DI + d)*LL + l] = sp;
}

// ---------------- selective scan, phase A: chunk-local, emit hfin + sum(delta) ----------------
__global__ void k_scanA(const float* __restrict__ A_logs) {
    int b = blockIdx.z, chunk = blockIdx.y, ch0 = blockIdx.x*16;
    int tid = threadIdx.x, warp = tid>>5, lane = tid&31, half = lane>>4, n = lane&15;
    int chl = warp*2 + half;
    int d = ch0 + chl;
    float Ac = -expf(A_logs[d*16+n]);
    __shared__ float sB[TT][16], sD[16][TT], sU[16][TT];
    float h = 0.f, ds = 0.f;
    int l0 = chunk*LC;
    for (int t0=0;t0<LC;t0+=TT){
        __syncthreads();
        #pragma unroll
        for (int r=0;r<4;r++){ int j=tid+r*256; int row=j>>4, col=j&15;
            sB[row][col] = d_Bs1[((size_t)b*LL + l0+t0+row)*16 + col]; }
        #pragma unroll
        for (int r=0;r<4;r++){ int j=tid+r*256; int ch=j>>6, i=j&63;
            size_t base = ((size_t)b*DI + ch0+ch)*LL + l0+t0;
            sD[ch][i] = d_deltaT[base+i];
            sU[ch][i] = d_ut[base+i]; }
        __syncthreads();
        #pragma unroll 16
        for (int i=0;i<TT;i++){
            float dly = sD[chl][i], uv = sU[chl][i];
            float a = __expf(dly*Ac);
            h = fmaf(a, h, dly*uv*sB[i][n]);
            ds += dly;
        }
    }
    size_t cb = (size_t)(b*NC+chunk)*DI + d;
    d_hfin[cb*16+n] = h;
    if (n==0) d_dsum[cb] = ds;
}

// ---------------- phase B: stitch chunks ----------------
__global__ void k_scanB(const float* __restrict__ A_logs) {
    int idx = blockIdx.x*blockDim.x + threadIdx.x;          // BD*DI*16
    int n = idx & 15; int d = (idx>>4) % DI; int b = idx/(16*DI);
    float Ac = -expf(A_logs[d*16+n]);
    float H = 0.f;
    for (int c=0;c<NC;c++){
        size_t cb = (size_t)(b*NC+c)*DI + d;
        d_hin[cb*16+n] = H;
        H = __expf(Ac*d_dsum[cb])*H + d_hfin[cb*16+n];
    }
}

// ---------------- phase C: replay with init state, emit y ----------------
__global__ void k_scanC(const float* __restrict__ A_logs, const float* __restrict__ Ds) {
    int b = blockIdx.z, chunk = blockIdx.y, ch0 = blockIdx.x*16;
    int tid = threadIdx.x, warp = tid>>5, lane = tid&31, half = lane>>4, n = lane&15;
    int chl = warp*2 + half;
    int d = ch0 + chl;
    float Ac = -expf(A_logs[d*16+n]);
    float Dd = Ds[d];
    size_t cb = (size_t)(b*NC+chunk)*DI + d;
    float h = d_hin[cb*16+n];
    __shared__ float sB[TT][16], sC[TT][16], sD[16][TT], sU[16][TT], sY[TT][16];
    int l0 = chunk*LC;
    for (int t0=0;t0<LC;t0+=TT){
        __syncthreads();
        #pragma unroll
        for (int r=0;r<4;r++){ int j=tid+r*256; int row=j>>4, col=j&15;
            size_t gidx = ((size_t)b*LL + l0+t0+row)*16 + col;
            sB[row][col] = d_Bs1[gidx];
            sC[row][col] = d_Cs1[gidx]; }
        #pragma unroll
        for (int r=0;r<4;r++){ int j=tid+r*256; int ch=j>>6, i=j&63;
            size_t base = ((size_t)b*DI + ch0+ch)*LL + l0+t0;
            sD[ch][i] = d_deltaT[base+i];
            sU[ch][i] = d_ut[base+i]; }
        __syncthreads();
        #pragma unroll 8
        for (int i=0;i<TT;i++){
            float dly = sD[chl][i], uv = sU[chl][i];
            float a = __expf(dly*Ac);
            h = fmaf(a, h, dly*uv*sB[i][n]);
            float yp = h * sC[i][n];
            yp += __shfl_xor_sync(~0u, yp, 8, 16);
            yp += __shfl_xor_sync(~0u, yp, 4, 16);
            yp += __shfl_xor_sync(~0u, yp, 2, 16);
            yp += __shfl_xor_sync(~0u, yp, 1, 16);
            if (n==0) sY[i][chl] = yp + uv*Dd;
        }
        __syncthreads();
        #pragma unroll
        for (int r=0;r<4;r++){ int j=tid+r*256; int row=j>>4, col=j&15;
            d_y[((size_t)b*LL + l0+t0+row)*DI + ch0+col] = sY[row][col]; }
    }
}

// ---------------- out_norm LN * silu(z) (warp per pixel, D=384) ----------------
__global__ void k_gate(const float* __restrict__ g, const float* __restrict__ bb) {
    int wid = threadIdx.x>>5, lane = threadIdx.x&31;
    int p = blockIdx.x*8 + wid;
    const float* row = d_y + (size_t)p*DI;
    float s=0.f, s2=0.f;
    for (int c=lane;c<DI;c+=32){ float v=row[c]; s+=v; s2+=v*v; }
    for (int o=16;o;o>>=1){ s+=__shfl_xor_sync(~0u,s,o); s2+=__shfl_xor_sync(~0u,s2,o); }
    float mean = s/DI, var = s2/DI - mean*mean;
    float rstd = rsqrtf(var + 1e-5f);
    for (int c=lane;c<DI;c+=32){
        float yn = (row[c]-mean)*rstd*g[c]+bb[c];
        float zv = d_xz[(size_t)p*(2*DI) + DI + c];
        d_gated[(size_t)p*DI+c] = yn * (zv/(1.f+__expf(-zv)));
    }
}

// ---------------- launcher ----------------
extern "C" void kernel_launch(void* const* d_in, const int* in_sizes, int n_in,
                              void* d_out, int out_size) {
    const float* x    = (const float*)d_in[0];
    const float* low  = (const float*)d_in[1];
    const float* ln_g = (const float*)d_in[2];
    const float* ln_b = (const float*)d_in[3];
    const float* ipw  = (const float*)d_in[4];
    const float* iplw = (const float*)d_in[5];
    const float* c2w  = (const float*)d_in[6];
    const float* c2b  = (const float*)d_in[7];
    const float* xpw  = (const float*)d_in[8];
    const float* xpwl = (const float*)d_in[9];
    const float* cdtw = (const float*)d_in[10];
    const float* cBw  = (const float*)d_in[11];
    const float* cCw  = (const float*)d_in[12];
    const float* sgbw1= (const float*)d_in[13];
    const float* sgbw2= (const float*)d_in[14];
    const float* sgcw1= (const float*)d_in[15];
    const float* sgcw2= (const float*)d_in[16];
    const float* dtw  = (const float*)d_in[17];
    const float* dtb  = (const float*)d_in[18];
    const float* Alog = (const float*)d_in[19];
    const float* Ds   = (const float*)d_in[20];
    const float* ong  = (const float*)d_in[21];
    const float* onb  = (const float*)d_in[22];
    const float* opw  = (const float*)d_in[23];
    float* out = (float*)d_out;

    void *p_xn, *p_xz, *p_lowp, *p_xs, *p_xdbl, *p_ldbl, *p_gated;
    void *p_Wt1, *p_Wt2, *p_Wt3, *p_Wtx, *p_Wtxl;
    cudaGetSymbolAddress(&p_xn, d_xn);
    cudaGetSymbolAddress(&p_xz, d_xz);
    cudaGetSymbolAddress(&p_lowp, d_lowp);
    cudaGetSymbolAddress(&p_xs, d_xs);
    cudaGetSymbolAddress(&p_xdbl, d_xdbl);
    cudaGetSymbolAddress(&p_ldbl, d_ldbl);
    cudaGetSymbolAddress(&p_gated, d_gated);
    cudaGetSymbolAddress(&p_Wt1, d_Wt1);
    cudaGetSymbolAddress(&p_Wt2, d_Wt2);
    cudaGetSymbolAddress(&p_Wt3, d_Wt3);
    cudaGetSymbolAddress(&p_Wtx, d_Wtx);
    cudaGetSymbolAddress(&p_Wtxl, d_Wtxl);

    // 0) weight prep
    k_prep<<<(CM*2*DI + CM*DI + DI*CM + 2*DI*64 + 255)/256, 256>>>(ipw, iplw, opw, xpw, xpwl);
    // 1) pre-LN
    k_ln<<<PX/8, 256>>>(x, ln_g, ln_b);
    // 2) in_proj: xn[16384,192] x Wt1[192,768] -> xz
    k_gemm<<<dim3(768/64, PX/64), 256>>>((const float*)p_xn, (const float*)p_Wt1,
                                         (float*)p_xz, CM, 2*DI, nullptr);
    // 3) in_proj_low: low x Wt2 -> lowp
    k_gemm<<<dim3(DI/64, PX/64), 256>>>(low, (const float*)p_Wt2,
                                        (float*)p_lowp, CM, DI, nullptr);
    // 4) depthwise conv 3x3 + silu -> xs
    k_conv2d<<<(size_t)PX*DI/256, 256>>>(c2w, c2b);
    // 5) transpose u
    k_transpose<<<dim3(DI/32, LL/32, BD), dim3(32,8)>>>();
    // 6) x_proj (high): xs x Wtx -> xdbl
    k_gemm<<<dim3(1, PX/64), 256>>>((const float*)p_xs, (const float*)p_Wtx,
                                    (float*)p_xdbl, DI, 64, nullptr);
    // 7) x_proj (low): lowp x Wtxl -> ldbl
    k_gemm<<<dim3(1, PX/64), 256>>>((const float*)p_lowp, (const float*)p_Wtxl,
                                    (float*)p_ldbl, DI, 64, nullptr);
    // 8) combine + SimpleGates
    k_combine<<<2*PX/256, 256>>>(sgbw1, sgbw2, sgcw1, sgcw2);
    // 9) residual dilated dwconv1d on dts/Bs/Cs
    k_dwconv1d<<<3*BD*LL*16/256, 256>>>(cdtw, cBw, cCw);
    // 10) delta projection + softplus (channel-major out)
    k_delta<<<(size_t)BD*DI*LL/256, 256>>>(dtw, dtb);
    // 11) selective scan (3 phases)
    k_scanA<<<dim3(DI/16, NC, BD), 256>>>(Alog);
    k_scanB<<<BD*DI*16/256, 256>>>(Alog);
    k_scanC<<<dim3(DI/16, NC, BD), 256>>>(Alog, Ds);
    // 12) out_norm LN * silu(z)
    k_gate<<<PX/8, 256>>>(ong, onb);
    // 13) out_proj + residual x
    k_gemm<<<dim3(CM/64, PX/64), 256>>>((const float*)p_gated, (const float*)p_Wt3,
                                        out, DI, CM, x);
}

// round 2
// speedup vs baseline: 1.2938x; 1.2938x over previous
#include <cuda_runtime.h>
#include <math.h>

#define BD 4
#define LL 4096
#define PX (BD*LL)        // 16384 pixels
#define CM 192
#define DI 384
#define RK 12
#define NS 16
#define NC 8              // scan chunks
#define LC (LL/NC)        // 512
#define TT 64             // scan sub-tile

// ---------------- scratch (device globals; no mallocs allowed) ----------------
__device__ float d_xn   [PX*CM];
__device__ float d_xz   [(size_t)PX*2*DI];
__device__ float d_lowp [(size_t)PX*DI];
__device__ float d_xs   [(size_t)PX*DI];     // u, pixel-major [p][d]
__device__ float d_ut   [(size_t)BD*DI*LL];  // u, channel-major [b][d][l]
__device__ float d_deltaT[(size_t)BD*DI*LL]; // delta, channel-major
__device__ float d_xdbl [PX*64];
__device__ float d_ldbl [PX*64];
__device__ float d_dts0 [PX*16];
__device__ float d_Bs0  [PX*16];
__device__ float d_Cs0  [PX*16];
__device__ float d_dts1 [PX*16];
__device__ float d_Bs1  [PX*16];
__device__ float d_Cs1  [PX*16];
__device__ float d_y    [(size_t)PX*DI];
__device__ float d_gated[(size_t)PX*DI];
__device__ float d_Wt1  [CM*2*DI];   // in_proj^T  [k][co]
__device__ float d_Wt2  [CM*DI];     // in_proj_low^T
__device__ float d_Wt3  [DI*CM];     // out_proj^T
__device__ float d_Wtx  [DI*64];     // x_proj^T padded to 64 cols
__device__ float d_Wtxl [DI*64];     // x_proj_low^T padded
__device__ float d_hfin [BD*NC*DI*NS];
__device__ float d_dsum [BD*NC*DI];
__device__ float d_hin  [BD*NC*DI*NS];

// ---------------- weight prep: transpose to k-major ----------------
__global__ void k_prep(const float* __restrict__ ipw, const float* __restrict__ iplw,
                       const float* __restrict__ opw, const float* __restrict__ xpw,
                       const float* __restrict__ xpwl) {
    int i = blockIdx.x*blockDim.x + threadIdx.x;
    const int n1 = CM*2*DI, n2 = CM*DI, n3 = DI*CM, n4 = DI*64;
    if (i < n1) { int k=i/(2*DI), co=i%(2*DI); d_Wt1[i]=ipw[co*CM+k]; return; }
    i -= n1;
    if (i < n2) { int k=i/DI, co=i%DI; d_Wt2[i]=iplw[co*CM+k]; return; }
    i -= n2;
    if (i < n3) { int k=i/CM, co=i%CM; d_Wt3[i]=opw[co*DI+k]; return; }
    i -= n3;
    if (i < n4) { int k=i/64, co=i%64; d_Wtx[i]=(co<44)? xpw[co*DI+k]:0.f; return; }
    i -= n4;
    if (i < n4) { int k=i/64, co=i%64; d_Wtxl[i]=(co<44)? xpwl[co*DI+k]:0.f; return; }
}

// ---------------- LayerNorm (warp per pixel) ----------------
__global__ void k_ln(const float* __restrict__ x, const float* __restrict__ g,
                     const float* __restrict__ b) {
    int wid = threadIdx.x>>5, lane = threadIdx.x&31;
    int p = blockIdx.x*8 + wid;
    const float* row = x + (size_t)p*CM;
    float s=0.f, s2=0.f;
    for (int c=lane;c<CM;c+=32){ float v=row[c]; s+=v; s2+=v*v; }
    for (int o=16;o;o>>=1){ s+=__shfl_xor_sync(~0u,s,o); s2+=__shfl_xor_sync(~0u,s2,o); }
    float mean = s/CM, var = s2/CM - mean*mean;
    float rstd = rsqrtf(var + 1e-5f);
    for (int c=lane;c<CM;c+=32)
        d_xn[(size_t)p*CM+c] = (row[c]-mean)*rstd*g[c]+b[c];
}

// ---------------- TF32 tensor-core GEMM: C[M,N] = A[M,K] * W[K,N] (+resid) ----------------
__device__ __forceinline__ unsigned f2tf(float f){
    unsigned u; asm("cvt.rna.tf32.f32 %0, %1;" : "=r"(u) : "f"(f)); return u;
}

__global__ __launch_bounds__(256) void k_gemm_tf32(
        const float* __restrict__ A, const float* __restrict__ W,
        float* __restrict__ C, int K, int N, const float* __restrict__ resid) {
    // CTA tile 128x64, BK=32. 8 warps: warp_m = warp&3 (32 rows), warp_n = warp>>2 (32 cols).
    __shared__ unsigned As[128*36];     // [m][k], row pad 36 -> conflict-free frag loads
    __shared__ unsigned Bs[4*64*9];     // [kstep][n][kk], pad 9 -> ~conflict-free
    int m0 = blockIdx.y*128, n0 = blockIdx.x*64;
    int tid = threadIdx.x, lane = tid&31, warp = tid>>5;
    int wm = (warp&3)*32, wn = (warp>>2)*32;
    float acc[2][4][4];
    #pragma unroll
    for (int i=0;i<2;i++)
        #pragma unroll
        for (int j=0;j<4;j++)
            #pragma unroll
            for (int r=0;r<4;r++) acc[i][j][r]=0.f;

    for (int k0=0;k0<K;k0+=32){
        __syncthreads();
        // A: 128x32 floats, 4 x float4 per thread, conflict-free uint4 smem stores
        #pragma unroll
        for (int r=0;r<4;r++){
            int idx4 = tid + r*256;
            int m = idx4>>3, kq = (idx4&7)*4;
            float4 v = *(const float4*)&A[(size_t)(m0+m)*K + k0+kq];
            uint4 s;
            s.x=f2tf(v.x); s.y=f2tf(v.y); s.z=f2tf(v.z); s.w=f2tf(v.w);
            *(uint4*)&As[m*36 + kq] = s;
        }
        // B: 32x64 floats, transpose-scatter into [kstep][n][kk]
        #pragma unroll
        for (int r=0;r<2;r++){
            int idx4 = tid + r*256;
            int k = idx4>>4, nq = (idx4&15)*4;
            float4 v = *(const float4*)&W[(size_t)(k0+k)*N + n0+nq];
            int s = k>>3, kk = k&7;
            Bs[(s*64 + nq+0)*9 + kk] = f2tf(v.x);
            Bs[(s*64 + nq+1)*9 + kk] = f2tf(v.y);
            Bs[(s*64 + nq+2)*9 + kk] = f2tf(v.z);
            Bs[(s*64 + nq+3)*9 + kk] = f2tf(v.w);
        }
        __syncthreads();
        #pragma unroll
        for (int s=0;s<4;s++){
            unsigned a[2][4], b[4][2];
            #pragma unroll
            for (int i=0;i<2;i++){
                int mb = wm + i*16 + (lane>>2);
                int kb = s*8 + (lane&3);
                a[i][0] = As[mb*36 + kb];
                a[i][1] = As[(mb+8)*36 + kb];
                a[i][2] = As[mb*36 + kb+4];
                a[i][3] = As[(mb+8)*36 + kb+4];
            }
            #pragma unroll
            for (int j=0;j<4;j++){
                int nb = wn + j*8 + (lane>>2);
                int kk = lane&3;
                b[j][0] = Bs[(s*64+nb)*9 + kk];
                b[j][1] = Bs[(s*64+nb)*9 + kk+4];
            }
            #pragma unroll
            for (int i=0;i<2;i++)
                #pragma unroll
                for (int j=0;j<4;j++){
                    asm volatile(
                        "mma.sync.aligned.m16n8k8.row.col.f32.tf32.tf32.f32 "
                        "{%0,%1,%2,%3}, {%4,%5,%6,%7}, {%8,%9}, {%0,%1,%2,%3};"
                        : "+f"(acc[i][j][0]),"+f"(acc[i][j][1]),
                          "+f"(acc[i][j][2]),"+f"(acc[i][j][3])
                        : "r"(a[i][0]),"r"(a[i][1]),"r"(a[i][2]),"r"(a[i][3]),
                          "r"(b[j][0]),"r"(b[j][1]));
                }
        }
    }
    // epilogue
    int rr = lane>>2, c2 = (lane&3)*2;
    #pragma unroll
    for (int i=0;i<2;i++){
        #pragma unroll
        for (int j=0;j<4;j++){
            int m = m0 + wm + i*16 + rr;
            int n = n0 + wn + j*8 + c2;
            float v0 = acc[i][j][0], v1 = acc[i][j][1];
            float v2 = acc[i][j][2], v3 = acc[i][j][3];
            if (resid){
                v0 += resid[(size_t)m*N+n];   v1 += resid[(size_t)m*N+n+1];
                v2 += resid[(size_t)(m+8)*N+n]; v3 += resid[(size_t)(m+8)*N+n+1];
            }
            C[(size_t)m*N+n] = v0;   C[(size_t)m*N+n+1] = v1;
            C[(size_t)(m+8)*N+n] = v2; C[(size_t)(m+8)*N+n+1] = v3;
        }
    }
}

// ---------------- depthwise 3x3 conv + bias + SiLU ----------------
__global__ void k_conv2d(const float* __restrict__ w, const float* __restrict__ bias) {
    int idx = blockIdx.x*blockDim.x + threadIdx.x;          // PX*DI
    int d = idx % DI; int l = (idx/DI) & (LL-1); int b = idx/(DI*LL);
    int h = l>>6, wc = l&63;
    float acc = bias[d];
    #pragma unroll
    for (int dy=0;dy<3;dy++){
        int hh = h+dy-1; if ((unsigned)hh >= 64u) continue;
        #pragma unroll
        for (int dx=0;dx<3;dx++){
            int ww = wc+dx-1; if ((unsigned)ww >= 64u) continue;
            acc = fmaf(w[d*9+dy*3+dx],
                       d_xz[((size_t)(b*LL + (hh<<6)+ww))*(2*DI) + d], acc);
        }
    }
    d_xs[(size_t)(b*LL+l)*DI + d] = acc / (1.f + __expf(-acc));
}

// ---------------- transpose u: [b][l][d] -> [b][d][l] ----------------
__global__ void k_transpose() {
    __shared__ float t[32][33];
    int b = blockIdx.z, l0 = blockIdx.y*32, d0 = blockIdx.x*32;
    int tx = threadIdx.x, ty = threadIdx.y;
    #pragma unroll
    for (int r=0;r<32;r+=8)
        t[ty+r][tx] = d_xs[(size_t)(b*LL + l0+ty+r)*DI + d0+tx];
    __syncthreads();
    #pragma unroll
    for (int r=0;r<32;r+=8)
        d_ut[((size_t)b*DI + d0+ty+r)*LL + l0+tx] = t[tx][ty+r];
}

// ---------------- combine branches + SimpleGate on low B/C ----------------
__global__ void k_combine(const float* __restrict__ w1b, const float* __restrict__ w2b,
                          const float* __restrict__ w1c, const float* __restrict__ w2c) {
    __shared__ float s_w1b[192*16], s_w2b[16*96], s_w1c[192*16], s_w2c[16*96];
    int tid = threadIdx.x;
    for (int i=tid;i<192*16;i+=256){ s_w1b[i]=w1b[i]; s_w1c[i]=w1c[i]; }
    for (int i=tid;i<16*96;i+=256){ s_w2b[i]=w2b[i]; s_w2c[i]=w2c[i]; }
    __syncthreads();
    int gi = blockIdx.x*256 + tid;                          // 2*PX
    int p = gi>>1, br = gi&1;
    const float* xd = d_xdbl + (size_t)p*64;
    const float* ld = d_ldbl + (size_t)p*64;
    const float* w1 = br? s_w1c : s_w1b;
    const float* w2 = br? s_w2c : s_w2b;
    int off = br? 28 : 12;
    float xv[16], acc[16];
    #pragma unroll
    for (int c=0;c<16;c++){ xv[c]=ld[off+c]; acc[c]=0.f; }
    for (int hh=0;hh<96;hh++){
        float y1=0.f, y2=0.f;
        #pragma unroll
        for (int c=0;c<16;c++){
            y1 = fmaf(w1[hh*16+c], xv[c], y1);
            y2 = fmaf(w1[(hh+96)*16+c], xv[c], y2);
        }
        float g = 0.5f*y1*(1.f+erff(y1*0.70710678118f))*y2;
        #pragma unroll
        for (int c=0;c<16;c++) acc[c] = fmaf(g, w2[c*96+hh], acc[c]);
    }
    float* outp = br? d_Cs0 : d_Bs0;
    #pragma unroll
    for (int c=0;c<16;c++) outp[(size_t)p*16+c] = xd[off+c] + acc[c];
    if (br==0){
        #pragma unroll
        for (int r=0;r<16;r++)
            d_dts0[(size_t)p*16+r] = (r<12)? (xd[r]+ld[r]) : 0.f;
    }
}

// ---------------- residual dilated (dil=2, K=15) depthwise conv1d ----------------
__global__ void k_dwconv1d(const float* __restrict__ wdt, const float* __restrict__ wB,
                           const float* __restrict__ wC) {
    int idx = blockIdx.x*blockDim.x + threadIdx.x;          // 3 * BD*LL*16
    const int per = BD*LL*16;
    int t = idx / per; int rem = idx % per;
    int c = rem & 15; int l = (rem>>4) & (LL-1); int b = rem >> 16;
    const float* in; float* out; const float* w; int nc;
    if (t==0){ in=d_dts0; out=d_dts1; w=wdt; nc=12; }
    else if (t==1){ in=d_Bs0; out=d_Bs1; w=wB; nc=16; }
    else { in=d_Cs0; out=d_Cs1; w=wC; nc=16; }
    size_t base = (size_t)b*LL*16;
    if (c < nc){
        float accv = in[base + (size_t)l*16 + c];
        #pragma unroll
        for (int k=0;k<15;k++){
            int ll = l + 2*k - 14;
            if ((unsigned)ll < (unsigned)LL)
                accv = fmaf(w[c*15+k], in[base + (size_t)ll*16 + c], accv);
        }
        out[base + (size_t)l*16 + c] = accv;
    } else out[base + (size_t)l*16 + c] = 0.f;
}

// ---------------- delta = softplus(dts @ dt_w^T + b), write channel-major ----------------
__global__ void k_delta(const float* __restrict__ dtw, const float* __restrict__ dtb) {
    int idx = blockIdx.x*blockDim.x + threadIdx.x;          // BD*DI*LL
    int l = idx & (LL-1); int t = idx >> 12; int d = t % DI; int b = t / DI;
    const float* row = d_dts1 + ((size_t)b*LL + l)*16;
    float acc = dtb[d];
    #pragma unroll
    for (int r=0;r<12;r++) acc = fmaf(row[r], dtw[d*12+r], acc);
    float sp = (acc > 20.f)? acc : log1pf(__expf(acc));
    d_deltaT[((size_t)b*DI + d)*LL + l] = sp;
}

// ---------------- selective scan, phase A: chunk-local, emit hfin + sum(delta) ----------------
__global__ void k_scanA(const float* __restrict__ A_logs) {
    int b = blockIdx.z, chunk = blockIdx.y, ch0 = blockIdx.x*16;
    int tid = threadIdx.x, warp = tid>>5, lane = tid&31, half = lane>>4, n = lane&15;
    int chl = warp*2 + half;
    int d = ch0 + chl;
    float Ac = -expf(A_logs[d*16+n]);
    __shared__ float sB[TT][16], sD[16][TT], sU[16][TT];
    float h = 0.f, ds = 0.f;
    int l0 = chunk*LC;
    for (int t0=0;t0<LC;t0+=TT){
        __syncthreads();
        #pragma unroll
        for (int r=0;r<4;r++){ int j=tid+r*256; int row=j>>4, col=j&15;
            sB[row][col] = d_Bs1[((size_t)b*LL + l0+t0+row)*16 + col]; }
        #pragma unroll
        for (int r=0;r<4;r++){ int j=tid+r*256; int ch=j>>6, i=j&63;
            size_t base = ((size_t)b*DI + ch0+ch)*LL + l0+t0;
            sD[ch][i] = d_deltaT[base+i];
            sU[ch][i] = d_ut[base+i]; }
        __syncthreads();
        #pragma unroll 16
        for (int i=0;i<TT;i++){
            float dly = sD[chl][i], uv = sU[chl][i];
            float a = __expf(dly*Ac);
            h = fmaf(a, h, dly*uv*sB[i][n]);
            ds += dly;
        }
    }
    size_t cb = (size_t)(b*NC+chunk)*DI + d;
    d_hfin[cb*16+n] = h;
    if (n==0) d_dsum[cb] = ds;
}

// ---------------- phase B: stitch chunks ----------------
__global__ void k_scanB(const float* __restrict__ A_logs) {
    int idx = blockIdx.x*blockDim.x + threadIdx.x;          // BD*DI*16
    int n = idx & 15; int d = (idx>>4) % DI; int b = idx/(16*DI);
    float Ac = -expf(A_logs[d*16+n]);
    float H = 0.f;
    for (int c=0;c<NC;c++){
        size_t cb = (size_t)(b*NC+c)*DI + d;
        d_hin[cb*16+n] = H;
        H = __expf(Ac*d_dsum[cb])*H + d_hfin[cb*16+n];
    }
}

// ---------------- phase C: replay with init state, emit y ----------------
__global__ void k_scanC(const float* __restrict__ A_logs, const float* __restrict__ Ds) {
    int b = blockIdx.z, chunk = blockIdx.y, ch0 = blockIdx.x*16;
    int tid = threadIdx.x, warp = tid>>5, lane = tid&31, half = lane>>4, n = lane&15;
    int chl = warp*2 + half;
    int d = ch0 + chl;
    float Ac = -expf(A_logs[d*16+n]);
    float Dd = Ds[d];
    size_t cb = (size_t)(b*NC+chunk)*DI + d;
    float h = d_hin[cb*16+n];
    __shared__ float sB[TT][16], sC[TT][16], sD[16][TT], sU[16][TT], sY[TT][16];
    int l0 = chunk*LC;
    for (int t0=0;t0<LC;t0+=TT){
        __syncthreads();
        #pragma unroll
        for (int r=0;r<4;r++){ int j=tid+r*256; int row=j>>4, col=j&15;
            size_t gidx = ((size_t)b*LL + l0+t0+row)*16 + col;
            sB[row][col] = d_Bs1[gidx];
            sC[row][col] = d_Cs1[gidx]; }
        #pragma unroll
        for (int r=0;r<4;r++){ int j=tid+r*256; int ch=j>>6, i=j&63;
            size_t base = ((size_t)b*DI + ch0+ch)*LL + l0+t0;
            sD[ch][i] = d_deltaT[base+i];
            sU[ch][i] = d_ut[base+i]; }
        __syncthreads();
        #pragma unroll 8
        for (int i=0;i<TT;i++){
            float dly = sD[chl][i], uv = sU[chl][i];
            float a = __expf(dly*Ac);
            h = fmaf(a, h, dly*uv*sB[i][n]);
            float yp = h * sC[i][n];
            yp += __shfl_xor_sync(~0u, yp, 8, 16);
            yp += __shfl_xor_sync(~0u, yp, 4, 16);
            yp += __shfl_xor_sync(~0u, yp, 2, 16);
            yp += __shfl_xor_sync(~0u, yp, 1, 16);
            if (n==0) sY[i][chl] = yp + uv*Dd;
        }
        __syncthreads();
        #pragma unroll
        for (int r=0;r<4;r++){ int j=tid+r*256; int row=j>>4, col=j&15;
            d_y[((size_t)b*LL + l0+t0+row)*DI + ch0+col] = sY[row][col]; }
    }
}

// ---------------- out_norm LN * silu(z) (warp per pixel, D=384) ----------------
__global__ void k_gate(const float* __restrict__ g, const float* __restrict__ bb) {
    int wid = threadIdx.x>>5, lane = threadIdx.x&31;
    int p = blockIdx.x*8 + wid;
    const float* row = d_y + (size_t)p*DI;
    float s=0.f, s2=0.f;
    for (int c=lane;c<DI;c+=32){ float v=row[c]; s+=v; s2+=v*v; }
    for (int o=16;o;o>>=1){ s+=__shfl_xor_sync(~0u,s,o); s2+=__shfl_xor_sync(~0u,s2,o); }
    float mean = s/DI, var = s2/DI - mean*mean;
    float rstd = rsqrtf(var + 1e-5f);
    for (int c=lane;c<DI;c+=32){
        float yn = (row[c]-mean)*rstd*g[c]+bb[c];
        float zv = d_xz[(size_t)p*(2*DI) + DI + c];
        d_gated[(size_t)p*DI+c] = yn * (zv/(1.f+__expf(-zv)));
    }
}

// ---------------- launcher ----------------
extern "C" void kernel_launch(void* const* d_in, const int* in_sizes, int n_in,
                              void* d_out, int out_size) {
    const float* x    = (const float*)d_in[0];
    const float* low  = (const float*)d_in[1];
    const float* ln_g = (const float*)d_in[2];
    const float* ln_b = (const float*)d_in[3];
    const float* ipw  = (const float*)d_in[4];
    const float* iplw = (const float*)d_in[5];
    const float* c2w  = (const float*)d_in[6];
    const float* c2b  = (const float*)d_in[7];
    const float* xpw  = (const float*)d_in[8];
    const float* xpwl = (const float*)d_in[9];
    const float* cdtw = (const float*)d_in[10];
    const float* cBw  = (const float*)d_in[11];
    const float* cCw  = (const float*)d_in[12];
    const float* sgbw1= (const float*)d_in[13];
    const float* sgbw2= (const float*)d_in[14];
    const float* sgcw1= (const float*)d_in[15];
    const float* sgcw2= (const float*)d_in[16];
    const float* dtw  = (const float*)d_in[17];
    const float* dtb  = (const float*)d_in[18];
    const float* Alog = (const float*)d_in[19];
    const float* Ds   = (const float*)d_in[20];
    const float* ong  = (const float*)d_in[21];
    const float* onb  = (const float*)d_in[22];
    const float* opw  = (const float*)d_in[23];
    float* out = (float*)d_out;

    void *p_xn, *p_xz, *p_lowp, *p_xs, *p_xdbl, *p_ldbl, *p_gated;
    void *p_Wt1, *p_Wt2, *p_Wt3, *p_Wtx, *p_Wtxl;
    cudaGetSymbolAddress(&p_xn, d_xn);
    cudaGetSymbolAddress(&p_xz, d_xz);
    cudaGetSymbolAddress(&p_lowp, d_lowp);
    cudaGetSymbolAddress(&p_xs, d_xs);
    cudaGetSymbolAddress(&p_xdbl, d_xdbl);
    cudaGetSymbolAddress(&p_ldbl, d_ldbl);
    cudaGetSymbolAddress(&p_gated, d_gated);
    cudaGetSymbolAddress(&p_Wt1, d_Wt1);
    cudaGetSymbolAddress(&p_Wt2, d_Wt2);
    cudaGetSymbolAddress(&p_Wt3, d_Wt3);
    cudaGetSymbolAddress(&p_Wtx, d_Wtx);
    cudaGetSymbolAddress(&p_Wtxl, d_Wtxl);

    // 0) weight prep
    k_prep<<<(CM*2*DI + CM*DI + DI*CM + 2*DI*64 + 255)/256, 256>>>(ipw, iplw, opw, xpw, xpwl);
    // 1) pre-LN
    k_ln<<<PX/8, 256>>>(x, ln_g, ln_b);
    // 2) in_proj: xn[16384,192] x Wt1[192,768] -> xz
    k_gemm_tf32<<<dim3(768/64, PX/128), 256>>>((const float*)p_xn, (const float*)p_Wt1,
                                               (float*)p_xz, CM, 2*DI, nullptr);
    // 3) in_proj_low: low x Wt2 -> lowp
    k_gemm_tf32<<<dim3(DI/64, PX/128), 256>>>(low, (const float*)p_Wt2,
                                              (float*)p_lowp, CM, DI, nullptr);
    // 4) depthwise conv 3x3 + silu -> xs
    k_conv2d<<<(size_t)PX*DI/256, 256>>>(c2w, c2b);
    // 5) transpose u
    k_transpose<<<dim3(DI/32, LL/32, BD), dim3(32,8)>>>();
    // 6) x_proj (high): xs x Wtx -> xdbl
    k_gemm_tf32<<<dim3(1, PX/128), 256>>>((const float*)p_xs, (const float*)p_Wtx,
                                          (float*)p_xdbl, DI, 64, nullptr);
    // 7) x_proj (low): lowp x Wtxl -> ldbl
    k_gemm_tf32<<<dim3(1, PX/128), 256>>>((const float*)p_lowp, (const float*)p_Wtxl,
                                          (float*)p_ldbl, DI, 64, nullptr);
    // 8) combine + SimpleGates
    k_combine<<<2*PX/256, 256>>>(sgbw1, sgbw2, sgcw1, sgcw2);
    // 9) residual dilated dwconv1d on dts/Bs/Cs
    k_dwconv1d<<<3*BD*LL*16/256, 256>>>(cdtw, cBw, cCw);
    // 10) delta projection + softplus (channel-major out)
    k_delta<<<(size_t)BD*DI*LL/256, 256>>>(dtw, dtb);
    // 11) selective scan (3 phases)
    k_scanA<<<dim3(DI/16, NC, BD), 256>>>(Alog);
    k_scanB<<<BD*DI*16/256, 256>>>(Alog);
    k_scanC<<<dim3(DI/16, NC, BD), 256>>>(Alog, Ds);
    // 12) out_norm LN * silu(z)
    k_gate<<<PX/8, 256>>>(ong, onb);
    // 13) out_proj + residual x
    k_gemm_tf32<<<dim3(CM/64, PX/128), 256>>>((const float*)p_gated, (const float*)p_Wt3,
                                              out, DI, CM, x);
}

// round 3
// speedup vs baseline: 1.6355x; 1.2641x over previous
#include <cuda_runtime.h>
#include <math.h>

#define BD 4
#define LL 4096
#define PX (BD*LL)        // 16384 pixels
#define CM 192
#define DI 384
#define RK 12
#define NS 16
#define NC 8              // scan chunks
#define LC (LL/NC)        // 512
#define TT 64             // scan sub-tile

// ---------------- scratch (device globals; no mallocs allowed) ----------------
__device__ float d_xn   [PX*CM];
__device__ float d_xz   [(size_t)PX*2*DI];
__device__ float d_lowp [(size_t)PX*DI];
__device__ float d_xs   [(size_t)PX*DI];     // u, pixel-major [p][d]
__device__ float d_ut   [(size_t)BD*DI*LL];  // u, channel-major [b][d][l]
__device__ float d_deltaT[(size_t)BD*DI*LL]; // delta, channel-major
__device__ float d_xdbl [PX*64];
__device__ float d_ldbl [PX*64];
__device__ float d_dts0 [PX*16];
__device__ float d_Bs0  [PX*16];
__device__ float d_Cs0  [PX*16];
__device__ float d_dts1 [PX*16];
__device__ float d_Bs1  [PX*16];
__device__ float d_Cs1  [PX*16];
__device__ float d_y    [(size_t)PX*DI];
__device__ float d_gated[(size_t)PX*DI];
__device__ float d_Wt1  [CM*2*DI];   // in_proj^T  [k][co]
__device__ float d_Wt2  [CM*DI];     // in_proj_low^T
__device__ float d_Wt3  [DI*CM];     // out_proj^T
__device__ float d_Wtx  [DI*64];     // x_proj^T padded to 64 cols
__device__ float d_Wtxl [DI*64];     // x_proj_low^T padded
__device__ float d_hfin [BD*NC*DI*NS];
__device__ float d_dsum [BD*NC*DI];
__device__ float d_hin  [BD*NC*DI*NS];

// ---------------- weight prep: transpose to k-major ----------------
__global__ void k_prep(const float* __restrict__ ipw, const float* __restrict__ iplw,
                       const float* __restrict__ opw, const float* __restrict__ xpw,
                       const float* __restrict__ xpwl) {
    int i = blockIdx.x*blockDim.x + threadIdx.x;
    const int n1 = CM*2*DI, n2 = CM*DI, n3 = DI*CM, n4 = DI*64;
    if (i < n1) { int k=i/(2*DI), co=i%(2*DI); d_Wt1[i]=ipw[co*CM+k]; return; }
    i -= n1;
    if (i < n2) { int k=i/DI, co=i%DI; d_Wt2[i]=iplw[co*CM+k]; return; }
    i -= n2;
    if (i < n3) { int k=i/CM, co=i%CM; d_Wt3[i]=opw[co*DI+k]; return; }
    i -= n3;
    if (i < n4) { int k=i/64, co=i%64; d_Wtx[i]=(co<44)? xpw[co*DI+k]:0.f; return; }
    i -= n4;
    if (i < n4) { int k=i/64, co=i%64; d_Wtxl[i]=(co<44)? xpwl[co*DI+k]:0.f; return; }
}

// ---------------- LayerNorm (warp per pixel) ----------------
__global__ void k_ln(const float* __restrict__ x, const float* __restrict__ g,
                     const float* __restrict__ b) {
    int wid = threadIdx.x>>5, lane = threadIdx.x&31;
    int p = blockIdx.x*8 + wid;
    const float* row = x + (size_t)p*CM;
    float s=0.f, s2=0.f;
    for (int c=lane;c<CM;c+=32){ float v=row[c]; s+=v; s2+=v*v; }
    for (int o=16;o;o>>=1){ s+=__shfl_xor_sync(~0u,s,o); s2+=__shfl_xor_sync(~0u,s2,o); }
    float mean = s/CM, var = s2/CM - mean*mean;
    float rstd = rsqrtf(var + 1e-5f);
    for (int c=lane;c<CM;c+=32)
        d_xn[(size_t)p*CM+c] = (row[c]-mean)*rstd*g[c]+b[c];
}

// ---------------- TF32 tensor-core GEMM, register double-buffered ----------------
__global__ __launch_bounds__(256) void k_gemm_tf32(
        const float* __restrict__ A, const float* __restrict__ W,
        float* __restrict__ C, int K, int N, const float* __restrict__ resid) {
    // CTA tile 128x64, BK=32. 8 warps: warp_m = warp&3 (32 rows), warp_n = warp>>2 (32 cols).
    __shared__ unsigned As[128*36];     // [m][k], pad 36 -> conflict-free frag loads
    __shared__ unsigned Bs[4*64*9];     // [kstep][n][kk]
    int m0 = blockIdx.y*128, n0 = blockIdx.x*64;
    int tid = threadIdx.x, lane = tid&31, warp = tid>>5;
    int wm = (warp&3)*32, wn = (warp>>2)*32;
    float acc[2][4][4];
    #pragma unroll
    for (int i=0;i<2;i++)
        #pragma unroll
        for (int j=0;j<4;j++)
            #pragma unroll
            for (int r=0;r<4;r++) acc[i][j][r]=0.f;

    // per-thread load coords
    int a_m = tid>>3, a_kq = (tid&7)*4;          // +r*32 rows
    int b_k0 = tid>>4, b_nq = (tid&15)*4;        // +r*16 k-rows

    float4 ra[4]; float4 rb[2];
    auto gload = [&](int k0){
        #pragma unroll
        for (int r=0;r<4;r++)
            ra[r] = *(const float4*)&A[(size_t)(m0+a_m+r*32)*K + k0+a_kq];
        #pragma unroll
        for (int r=0;r<2;r++)
            rb[r] = *(const float4*)&W[(size_t)(k0+b_k0+r*16)*N + n0+b_nq];
    };
    auto sstore = [&](){
        #pragma unroll
        for (int r=0;r<4;r++)
            *(uint4*)&As[(a_m+r*32)*36 + a_kq] = *(uint4*)&ra[r];
        #pragma unroll
        for (int r=0;r<2;r++){
            int k = b_k0 + r*16;
            int s = k>>3, kk = k&7;
            Bs[(s*64 + b_nq+0)*9 + kk] = __float_as_uint(rb[r].x);
            Bs[(s*64 + b_nq+1)*9 + kk] = __float_as_uint(rb[r].y);
            Bs[(s*64 + b_nq+2)*9 + kk] = __float_as_uint(rb[r].z);
            Bs[(s*64 + b_nq+3)*9 + kk] = __float_as_uint(rb[r].w);
        }
    };
    auto compute = [&](){
        #pragma unroll
        for (int s=0;s<4;s++){
            unsigned a[2][4], b[4][2];
            #pragma unroll
            for (int i=0;i<2;i++){
                int mb = wm + i*16 + (lane>>2);
                int kb = s*8 + (lane&3);
                a[i][0] = As[mb*36 + kb];
                a[i][1] = As[(mb+8)*36 + kb];
                a[i][2] = As[mb*36 + kb+4];
                a[i][3] = As[(mb+8)*36 + kb+4];
            }
            #pragma unroll
            for (int j=0;j<4;j++){
                int nb = wn + j*8 + (lane>>2);
                int kk = lane&3;
                b[j][0] = Bs[(s*64+nb)*9 + kk];
                b[j][1] = Bs[(s*64+nb)*9 + kk+4];
            }
            #pragma unroll
            for (int i=0;i<2;i++)
                #pragma unroll
                for (int j=0;j<4;j++){
                    asm volatile(
                        "mma.sync.aligned.m16n8k8.row.col.f32.tf32.tf32.f32 "
                        "{%0,%1,%2,%3}, {%4,%5,%6,%7}, {%8,%9}, {%0,%1,%2,%3};"
                        : "+f"(acc[i][j][0]),"+f"(acc[i][j][1]),
                          "+f"(acc[i][j][2]),"+f"(acc[i][j][3])
                        : "r"(a[i][0]),"r"(a[i][1]),"r"(a[i][2]),"r"(a[i][3]),
                          "r"(b[j][0]),"r"(b[j][1]));
                }
        }
    };

    gload(0);
    sstore();
    __syncthreads();
    for (int k0=32; k0<K; k0+=32){
        gload(k0);          // next tile in flight while computing current
        compute();
        __syncthreads();
        sstore();
        __syncthreads();
    }
    compute();

    // epilogue
    int rr = lane>>2, c2 = (lane&3)*2;
    #pragma unroll
    for (int i=0;i<2;i++){
        #pragma unroll
        for (int j=0;j<4;j++){
            int m = m0 + wm + i*16 + rr;
            int n = n0 + wn + j*8 + c2;
            float v0 = acc[i][j][0], v1 = acc[i][j][1];
            float v2 = acc[i][j][2], v3 = acc[i][j][3];
            if (resid){
                v0 += resid[(size_t)m*N+n];   v1 += resid[(size_t)m*N+n+1];
                v2 += resid[(size_t)(m+8)*N+n]; v3 += resid[(size_t)(m+8)*N+n+1];
            }
            C[(size_t)m*N+n] = v0;   C[(size_t)m*N+n+1] = v1;
            C[(size_t)(m+8)*N+n] = v2; C[(size_t)(m+8)*N+n+1] = v3;
        }
    }
}

// ---------------- depthwise 3x3 conv + bias + SiLU ----------------
__global__ void k_conv2d(const float* __restrict__ w, const float* __restrict__ bias) {
    int idx = blockIdx.x*blockDim.x + threadIdx.x;          // PX*DI
    int d = idx % DI; int l = (idx/DI) & (LL-1); int b = idx/(DI*LL);
    int h = l>>6, wc = l&63;
    float acc = bias[d];
    #pragma unroll
    for (int dy=0;dy<3;dy++){
        int hh = h+dy-1; if ((unsigned)hh >= 64u) continue;
        #pragma unroll
        for (int dx=0;dx<3;dx++){
            int ww = wc+dx-1; if ((unsigned)ww >= 64u) continue;
            acc = fmaf(w[d*9+dy*3+dx],
                       d_xz[((size_t)(b*LL + (hh<<6)+ww))*(2*DI) + d], acc);
        }
    }
    d_xs[(size_t)(b*LL+l)*DI + d] = acc / (1.f + __expf(-acc));
}

// ---------------- transpose u: [b][l][d] -> [b][d][l] ----------------
__global__ void k_transpose() {
    __shared__ float t[32][33];
    int b = blockIdx.z, l0 = blockIdx.y*32, d0 = blockIdx.x*32;
    int tx = threadIdx.x, ty = threadIdx.y;
    #pragma unroll
    for (int r=0;r<32;r+=8)
        t[ty+r][tx] = d_xs[(size_t)(b*LL + l0+ty+r)*DI + d0+tx];
    __syncthreads();
    #pragma unroll
    for (int r=0;r<32;r+=8)
        d_ut[((size_t)b*DI + d0+ty+r)*LL + l0+tx] = t[tx][ty+r];
}

// ---------------- combine branches + SimpleGate on low B/C ----------------
__global__ void k_combine(const float* __restrict__ w1b, const float* __restrict__ w2b,
                          const float* __restrict__ w1c, const float* __restrict__ w2c) {
    __shared__ float s_w1b[192*16], s_w2b[16*96], s_w1c[192*16], s_w2c[16*96];
    int tid = threadIdx.x;
    for (int i=tid;i<192*16;i+=256){ s_w1b[i]=w1b[i]; s_w1c[i]=w1c[i]; }
    for (int i=tid;i<16*96;i+=256){ s_w2b[i]=w2b[i]; s_w2c[i]=w2c[i]; }
    __syncthreads();
    int gi = blockIdx.x*256 + tid;                          // 2*PX
    int p = gi>>1, br = gi&1;
    const float* xd = d_xdbl + (size_t)p*64;
    const float* ld = d_ldbl + (size_t)p*64;
    const float* w1 = br? s_w1c : s_w1b;
    const float* w2 = br? s_w2c : s_w2b;
    int off = br? 28 : 12;
    float xv[16], acc[16];
    #pragma unroll
    for (int c=0;c<16;c++){ xv[c]=ld[off+c]; acc[c]=0.f; }
    for (int hh=0;hh<96;hh++){
        float y1=0.f, y2=0.f;
        #pragma unroll
        for (int c=0;c<16;c++){
            y1 = fmaf(w1[hh*16+c], xv[c], y1);
            y2 = fmaf(w1[(hh+96)*16+c], xv[c], y2);
        }
        float g = 0.5f*y1*(1.f+erff(y1*0.70710678118f))*y2;
        #pragma unroll
        for (int c=0;c<16;c++) acc[c] = fmaf(g, w2[c*96+hh], acc[c]);
    }
    float* outp = br? d_Cs0 : d_Bs0;
    #pragma unroll
    for (int c=0;c<16;c++) outp[(size_t)p*16+c] = xd[off+c] + acc[c];
    if (br==0){
        #pragma unroll
        for (int r=0;r<16;r++)
            d_dts0[(size_t)p*16+r] = (r<12)? (xd[r]+ld[r]) : 0.f;
    }
}

// ---------------- residual dilated (dil=2, K=15) depthwise conv1d ----------------
__global__ void k_dwconv1d(const float* __restrict__ wdt, const float* __restrict__ wB,
                           const float* __restrict__ wC) {
    int idx = blockIdx.x*blockDim.x + threadIdx.x;          // 3 * BD*LL*16
    const int per = BD*LL*16;
    int t = idx / per; int rem = idx % per;
    int c = rem & 15; int l = (rem>>4) & (LL-1); int b = rem >> 16;
    const float* in; float* out; const float* w; int nc;
    if (t==0){ in=d_dts0; out=d_dts1; w=wdt; nc=12; }
    else if (t==1){ in=d_Bs0; out=d_Bs1; w=wB; nc=16; }
    else { in=d_Cs0; out=d_Cs1; w=wC; nc=16; }
    size_t base = (size_t)b*LL*16;
    if (c < nc){
        float accv = in[base + (size_t)l*16 + c];
        #pragma unroll
        for (int k=0;k<15;k++){
            int ll = l + 2*k - 14;
            if ((unsigned)ll < (unsigned)LL)
                accv = fmaf(w[c*15+k], in[base + (size_t)ll*16 + c], accv);
        }
        out[base + (size_t)l*16 + c] = accv;
    } else out[base + (size_t)l*16 + c] = 0.f;
}

// ---------------- delta = softplus(dts @ dt_w^T + b): smem-tiled ----------------
__global__ __launch_bounds__(256) void k_delta(const float* __restrict__ dtw,
                                               const float* __restrict__ dtb) {
    __shared__ float sdts[64][17];
    __shared__ float sw[DI*12];
    __shared__ float sb[DI];
    int blk = blockIdx.x;                     // BD * LL/64 = 256 blocks
    int b = blk >> 6, l0 = (blk & 63) * 64;
    int tid = threadIdx.x;
    for (int i=tid; i<64*16; i+=256){ int l=i>>4, r=i&15;
        sdts[l][r] = d_dts1[((size_t)b*LL + l0+l)*16 + r]; }
    for (int i=tid; i<DI*12; i+=256) sw[i]=dtw[i];
    for (int i=tid; i<DI; i+=256) sb[i]=dtb[i];
    __syncthreads();
    int l = tid & 63, dg = tid >> 6;          // 4 d-groups of 96
    #pragma unroll 4
    for (int d = dg*96; d < dg*96+96; d++){
        float acc = sb[d];
        #pragma unroll
        for (int r=0;r<12;r++) acc = fmaf(sdts[l][r], sw[d*12+r], acc);
        float sp = (acc > 20.f)? acc : log1pf(__expf(acc));
        d_deltaT[((size_t)b*DI + d)*LL + l0 + l] = sp;
    }
}

// ---------------- selective scan, phase A: chunk-local, emit hfin + sum(delta) ----------------
__global__ void k_scanA(const float* __restrict__ A_logs) {
    int b = blockIdx.z, chunk = blockIdx.y, ch0 = blockIdx.x*16;
    int tid = threadIdx.x, warp = tid>>5, lane = tid&31, half = lane>>4, n = lane&15;
    int chl = warp*2 + half;
    int d = ch0 + chl;
    float Ac = -expf(A_logs[d*16+n]);
    __shared__ float sB[TT][16], sD[16][TT], sU[16][TT];
    float h = 0.f, ds = 0.f;
    int l0 = chunk*LC;
    for (int t0=0;t0<LC;t0+=TT){
        __syncthreads();
        #pragma unroll
        for (int r=0;r<4;r++){ int j=tid+r*256; int row=j>>4, col=j&15;
            sB[row][col] = d_Bs1[((size_t)b*LL + l0+t0+row)*16 + col]; }
        #pragma unroll
        for (int r=0;r<4;r++){ int j=tid+r*256; int ch=j>>6, i=j&63;
            size_t base = ((size_t)b*DI + ch0+ch)*LL + l0+t0;
            sD[ch][i] = d_deltaT[base+i];
            sU[ch][i] = d_ut[base+i]; }
        __syncthreads();
        #pragma unroll 16
        for (int i=0;i<TT;i++){
            float dly = sD[chl][i], uv = sU[chl][i];
            float a = __expf(dly*Ac);
            h = fmaf(a, h, dly*uv*sB[i][n]);
            ds += dly;
        }
    }
    size_t cb = (size_t)(b*NC+chunk)*DI + d;
    d_hfin[cb*16+n] = h;
    if (n==0) d_dsum[cb] = ds;
}

// ---------------- phase B: stitch chunks ----------------
__global__ void k_scanB(const float* __restrict__ A_logs) {
    int idx = blockIdx.x*blockDim.x + threadIdx.x;          // BD*DI*16
    int n = idx & 15; int d = (idx>>4) % DI; int b = idx/(16*DI);
    float Ac = -expf(A_logs[d*16+n]);
    float H = 0.f;
    for (int c=0;c<NC;c++){
        size_t cb = (size_t)(b*NC+c)*DI + d;
        d_hin[cb*16+n] = H;
        H = __expf(Ac*d_dsum[cb])*H + d_hfin[cb*16+n];
    }
}

// ---------------- phase C: replay with init state, emit y ----------------
__global__ void k_scanC(const float* __restrict__ A_logs, const float* __restrict__ Ds) {
    int b = blockIdx.z, chunk = blockIdx.y, ch0 = blockIdx.x*16;
    int tid = threadIdx.x, warp = tid>>5, lane = tid&31, half = lane>>4, n = lane&15;
    int chl = warp*2 + half;
    int d = ch0 + chl;
    float Ac = -expf(A_logs[d*16+n]);
    float Dd = Ds[d];
    size_t cb = (size_t)(b*NC+chunk)*DI + d;
    float h = d_hin[cb*16+n];
    __shared__ float sB[TT][16], sC[TT][16], sD[16][TT], sU[16][TT], sY[TT][16];
    int l0 = chunk*LC;
    for (int t0=0;t0<LC;t0+=TT){
        __syncthreads();
        #pragma unroll
        for (int r=0;r<4;r++){ int j=tid+r*256; int row=j>>4, col=j&15;
            size_t gidx = ((size_t)b*LL + l0+t0+row)*16 + col;
            sB[row][col] = d_Bs1[gidx];
            sC[row][col] = d_Cs1[gidx]; }
        #pragma unroll
        for (int r=0;r<4;r++){ int j=tid+r*256; int ch=j>>6, i=j&63;
            size_t base = ((size_t)b*DI + ch0+ch)*LL + l0+t0;
            sD[ch][i] = d_deltaT[base+i];
            sU[ch][i] = d_ut[base+i]; }
        __syncthreads();
        #pragma unroll 8
        for (int i=0;i<TT;i++){
            float dly = sD[chl][i], uv = sU[chl][i];
            float a = __expf(dly*Ac);
            h = fmaf(a, h, dly*uv*sB[i][n]);
            float yp = h * sC[i][n];
            yp += __shfl_xor_sync(~0u, yp, 8, 16);
            yp += __shfl_xor_sync(~0u, yp, 4, 16);
            yp += __shfl_xor_sync(~0u, yp, 2, 16);
            yp += __shfl_xor_sync(~0u, yp, 1, 16);
            if (n==0) sY[i][chl] = yp + uv*Dd;
        }
        __syncthreads();
        #pragma unroll
        for (int r=0;r<4;r++){ int j=tid+r*256; int row=j>>4, col=j&15;
            d_y[((size_t)b*LL + l0+t0+row)*DI + ch0+col] = sY[row][col]; }
    }
}

// ---------------- out_norm LN * silu(z) (warp per pixel, D=384) ----------------
__global__ void k_gate(const float* __restrict__ g, const float* __restrict__ bb) {
    int wid = threadIdx.x>>5, lane = threadIdx.x&31;
    int p = blockIdx.x*8 + wid;
    const float* row = d_y + (size_t)p*DI;
    float s=0.f, s2=0.f;
    for (int c=lane;c<DI;c+=32){ float v=row[c]; s+=v; s2+=v*v; }
    for (int o=16;o;o>>=1){ s+=__shfl_xor_sync(~0u,s,o); s2+=__shfl_xor_sync(~0u,s2,o); }
    float mean = s/DI, var = s2/DI - mean*mean;
    float rstd = rsqrtf(var + 1e-5f);
    for (int c=lane;c<DI;c+=32){
        float yn = (row[c]-mean)*rstd*g[c]+bb[c];
        float zv = d_xz[(size_t)p*(2*DI) + DI + c];
        d_gated[(size_t)p*DI+c] = yn * (zv/(1.f+__expf(-zv)));
    }
}

// ---------------- launcher ----------------
extern "C" void kernel_launch(void* const* d_in, const int* in_sizes, int n_in,
                              void* d_out, int out_size) {
    const float* x    = (const float*)d_in[0];
    const float* low  = (const float*)d_in[1];
    const float* ln_g = (const float*)d_in[2];
    const float* ln_b = (const float*)d_in[3];
    const float* ipw  = (const float*)d_in[4];
    const float* iplw = (const float*)d_in[5];
    const float* c2w  = (const float*)d_in[6];
    const float* c2b  = (const float*)d_in[7];
    const float* xpw  = (const float*)d_in[8];
    const float* xpwl = (const float*)d_in[9];
    const float* cdtw = (const float*)d_in[10];
    const float* cBw  = (const float*)d_in[11];
    const float* cCw  = (const float*)d_in[12];
    const float* sgbw1= (const float*)d_in[13];
    const float* sgbw2= (const float*)d_in[14];
    const float* sgcw1= (const float*)d_in[15];
    const float* sgcw2= (const float*)d_in[16];
    const float* dtw  = (const float*)d_in[17];
    const float* dtb  = (const float*)d_in[18];
    const float* Alog = (const float*)d_in[19];
    const float* Ds   = (const float*)d_in[20];
    const float* ong  = (const float*)d_in[21];
    const float* onb  = (const float*)d_in[22];
    const float* opw  = (const float*)d_in[23];
    float* out = (float*)d_out;

    void *p_xn, *p_xz, *p_lowp, *p_xs, *p_xdbl, *p_ldbl, *p_gated;
    void *p_Wt1, *p_Wt2, *p_Wt3, *p_Wtx, *p_Wtxl;
    cudaGetSymbolAddress(&p_xn, d_xn);
    cudaGetSymbolAddress(&p_xz, d_xz);
    cudaGetSymbolAddress(&p_lowp, d_lowp);
    cudaGetSymbolAddress(&p_xs, d_xs);
    cudaGetSymbolAddress(&p_xdbl, d_xdbl);
    cudaGetSymbolAddress(&p_ldbl, d_ldbl);
    cudaGetSymbolAddress(&p_gated, d_gated);
    cudaGetSymbolAddress(&p_Wt1, d_Wt1);
    cudaGetSymbolAddress(&p_Wt2, d_Wt2);
    cudaGetSymbolAddress(&p_Wt3, d_Wt3);
    cudaGetSymbolAddress(&p_Wtx, d_Wtx);
    cudaGetSymbolAddress(&p_Wtxl, d_Wtxl);

    // fork/join resources (host-side only; created once)
    static cudaStream_t s2 = nullptr;
    static cudaEvent_t evP = nullptr, evConv = nullptr, evLow = nullptr, evTr = nullptr;
    if (!s2){
        cudaStreamCreateWithFlags(&s2, cudaStreamNonBlocking);
        cudaEventCreateWithFlags(&evP,   cudaEventDisableTiming);
        cudaEventCreateWithFlags(&evConv,cudaEventDisableTiming);
        cudaEventCreateWithFlags(&evLow, cudaEventDisableTiming);
        cudaEventCreateWithFlags(&evTr,  cudaEventDisableTiming);
    }

    // 0) weight prep (main stream)
    k_prep<<<(CM*2*DI + CM*DI + DI*CM + 2*DI*64 + 255)/256, 256>>>(ipw, iplw, opw, xpw, xpwl);
    cudaEventRecord(evP, 0);

    // ---- side stream: low branch ----
    cudaStreamWaitEvent(s2, evP, 0);
    k_gemm_tf32<<<dim3(DI/64, PX/128), 256, 0, s2>>>(low, (const float*)p_Wt2,
                                                     (float*)p_lowp, CM, DI, nullptr);
    k_gemm_tf32<<<dim3(1, PX/128), 256, 0, s2>>>((const float*)p_lowp, (const float*)p_Wtxl,
                                                 (float*)p_ldbl, DI, 64, nullptr);
    cudaEventRecord(evLow, s2);

    // ---- main stream: high branch ----
    k_ln<<<PX/8, 256>>>(x, ln_g, ln_b);
    k_gemm_tf32<<<dim3(768/64, PX/128), 256>>>((const float*)p_xn, (const float*)p_Wt1,
                                               (float*)p_xz, CM, 2*DI, nullptr);
    k_conv2d<<<(size_t)PX*DI/256, 256>>>(c2w, c2b);
    cudaEventRecord(evConv, 0);
    // transpose on side stream, overlapped with x_proj-high/combine
    cudaStreamWaitEvent(s2, evConv, 0);
    k_transpose<<<dim3(DI/32, LL/32, BD), dim3(32,8), 0, s2>>>();
    cudaEventRecord(evTr, s2);

    k_gemm_tf32<<<dim3(1, PX/128), 256>>>((const float*)p_xs, (const float*)p_Wtx,
                                          (float*)p_xdbl, DI, 64, nullptr);
    cudaStreamWaitEvent(0, evLow, 0);
    k_combine<<<2*PX/256, 256>>>(sgbw1, sgbw2, sgcw1, sgcw2);
    k_dwconv1d<<<3*BD*LL*16/256, 256>>>(cdtw, cBw, cCw);
    k_delta<<<BD*(LL/64), 256>>>(dtw, dtb);
    cudaStreamWaitEvent(0, evTr, 0);
    k_scanA<<<dim3(DI/16, NC, BD), 256>>>(Alog);
    k_scanB<<<BD*DI*16/256, 256>>>(Alog);
    k_scanC<<<dim3(DI/16, NC, BD), 256>>>(Alog, Ds);
    k_gate<<<PX/8, 256>>>(ong, onb);
    k_gemm_tf32<<<dim3(CM/64, PX/128), 256>>>((const float*)p_gated, (const float*)p_Wt3,
                                              out, DI, CM, x);
}